// round 8
// baseline (speedup 1.0000x reference)
#include <cuda_runtime.h>
#include <cstdint>

// ---------------------------------------------------------------------------
// Problem constants
// ---------------------------------------------------------------------------
#define Bc 4
#define Hc 8
#define Tc 2048
#define Kc 512
#define KH 4096
#define M0 8192
#define INV4 0.2102241038134287f   // 512^(-0.25)

#define NA ((size_t)M0 * Kc)
#define NW ((size_t)Kc * KH)
#define NQ ((size_t)Bc * Hc * Tc * Kc)
#define NS ((size_t)Bc * Hc * Tc * Tc)

// ---------------------------------------------------------------------------
// Static device scratch
// ---------------------------------------------------------------------------
__device__ __align__(16) int8_t g_x1[NA], g_x2[NA];
__device__ float g_sx[M0];
__device__ __align__(16) int8_t g_wq1[NW], g_wq2[NW], g_wk1[NW], g_wk2[NW];
__device__ __align__(16) int8_t g_wv1[NW], g_wv2[NW], g_wu1[NW], g_wu2[NW];
__device__ float g_swq[KH], g_swk[KH], g_swv[KH], g_swu[Kc];
__device__ float g_wT32[NW];          // reused fp32 transpose scratch
__device__ float g_tmp32[NQ];         // reused: q32 / k32 / v32 / att32
__device__ float g_vT32[NQ];
__device__ __align__(16) int8_t g_q1[NQ], g_q2[NQ], g_k1[NQ], g_k2[NQ];
__device__ __align__(16) int8_t g_v1[NQ], g_v2[NQ];
__device__ float g_sq[Bc * Hc * Tc], g_sk[Bc * Hc * Tc], g_sv[Bc * Hc * Kc];
__device__ float g_s32[NS];
__device__ __align__(16) int8_t g_p1[NS], g_p2[NS];
__device__ float g_sp[Bc * Hc * Tc];
__device__ __align__(16) int8_t g_a1[NQ], g_a2[NQ];   // att digits (8192 x 4096)
__device__ float g_satt[M0];

// ---------------------------------------------------------------------------
// PTX helpers
// ---------------------------------------------------------------------------
__device__ __forceinline__ void cpa16(const void* smemPtr, const void* gptr) {
    uint32_t s = (uint32_t)__cvta_generic_to_shared(smemPtr);
    asm volatile("cp.async.cg.shared.global [%0], [%1], 16;" :: "r"(s), "l"(gptr));
}

__device__ __forceinline__ void ldsm4(uint32_t* d, const void* p) {
    uint32_t a = (uint32_t)__cvta_generic_to_shared(p);
    asm volatile("ldmatrix.sync.aligned.m8n8.x4.shared.b16 {%0,%1,%2,%3}, [%4];"
                 : "=r"(d[0]), "=r"(d[1]), "=r"(d[2]), "=r"(d[3]) : "r"(a));
}

// s8 MMA m16n8k32, s32 accumulate
__device__ __forceinline__ void imma(int* c, const uint32_t* a, const uint32_t* b) {
    asm volatile(
        "mma.sync.aligned.m16n8k32.row.col.s32.s8.s8.s32 "
        "{%0,%1,%2,%3}, {%4,%5,%6,%7}, {%8,%9}, {%0,%1,%2,%3};"
        : "+r"(c[0]), "+r"(c[1]), "+r"(c[2]), "+r"(c[3])
        : "r"(a[0]), "r"(a[1]), "r"(a[2]), "r"(a[3]), "r"(b[0]), "r"(b[1]));
}

// qkv layout index: row m = b*2048+t, col c = h*512+k  ->  [b,h,t,k]
__device__ __forceinline__ size_t qkv_idx(int m, int c) {
    return ((size_t)((m >> 11) * 8 + (c >> 9))) * ((size_t)Tc * Kc)
         + (size_t)(m & (Tc - 1)) * Kc + (c & (Kc - 1));
}

// ---------------------------------------------------------------------------
// int8 split GEMM: C = sa[m]*sb[n]*(A1*B1^T + (A1*B2^T + A2*B1^T)/254)
// A digits: [M][Kdim] k-contig; B digits: [N][Kdim] k-contig.
// CTA tile 128x128, BK=32, 8 warps of 32(M)x64(N), double-buffered cp.async.
// smem tile row = 64B: [d1 c0 | d1 c1 | d2 c0 | d2 c1], chunk-swizzled.
// mode 0: C + z*sCz + m*ldc + c (+bias); mode 1: qkv layout; mode 2: att layout
// ---------------------------------------------------------------------------
__device__ __forceinline__ void load_chunk_i8(
    int8_t* smbase,
    const int8_t* A1, const int8_t* A2, const int8_t* B1, const int8_t* B2,
    int Kdim, int k0, int tid)
{
#pragma unroll
    for (int i = 0; i < 4; i++) {
        const int id = tid + i * 256;              // 0..1023
        const int ch = id & 3, row = (id >> 2) & 127, t = id >> 9;
        const int8_t* src = t ? ((ch < 2) ? B1 : B2) : ((ch < 2) ? A1 : A2);
        const int kc = ch & 1;
        const int sw = ch ^ ((row >> 1) & 3);
        cpa16(smbase + t * 8192 + row * 64 + sw * 16,
              src + (size_t)row * Kdim + k0 + kc * 16);
    }
    asm volatile("cp.async.commit_group;" ::: "memory");
}

__global__ __launch_bounds__(256, 1)
void imma_gemm(const int8_t* __restrict__ A1, const int8_t* __restrict__ A2,
               const float* __restrict__ sa,
               const int8_t* __restrict__ B1, const int8_t* __restrict__ B2,
               const float* __restrict__ sb,
               float* __restrict__ C, const float* __restrict__ bias,
               int Kdim, int ldc,
               size_t sAz, size_t sBz, size_t sCz, int saz, int sbz, int mode)
{
    __shared__ __align__(128) int8_t sm[2][2 * 8192];

    const int tid = threadIdx.x, lane = tid & 31, warp = tid >> 5;
    const int z = blockIdx.z;
    const int blockM = blockIdx.y * 128, blockN = blockIdx.x * 128;
    const int m0 = (warp >> 1) * 32, n0 = (warp & 1) * 64;

    const int8_t* gA1 = A1 + (size_t)z * sAz + (size_t)blockM * Kdim;
    const int8_t* gA2 = A2 + (size_t)z * sAz + (size_t)blockM * Kdim;
    const int8_t* gB1 = B1 + (size_t)z * sBz + (size_t)blockN * Kdim;
    const int8_t* gB2 = B2 + (size_t)z * sBz + (size_t)blockN * Kdim;
    const float* saP = sa + (size_t)z * saz;
    const float* sbP = sb + (size_t)z * sbz;

    int acc1[2][8][4], acc2[2][8][4];
#pragma unroll
    for (int a = 0; a < 2; a++)
#pragma unroll
        for (int b = 0; b < 8; b++)
#pragma unroll
            for (int c = 0; c < 4; c++) { acc1[a][b][c] = 0; acc2[a][b][c] = 0; }

    const int laneA_r = lane & 15;
    const int laneA_c = lane >> 4;                       // 0/1
    const int laneB_r = (lane & 7) | ((lane >> 1) & 8);
    const int laneB_c = (lane >> 3) & 1;

    const int nk = Kdim >> 5;
    load_chunk_i8(sm[0], gA1, gA2, gB1, gB2, Kdim, 0, tid);

    for (int i = 0; i < nk; i++) {
        if (i + 1 < nk) {
            load_chunk_i8(sm[(i + 1) & 1], gA1, gA2, gB1, gB2, Kdim, (i + 1) << 5, tid);
            asm volatile("cp.async.wait_group 1;" ::: "memory");
        } else {
            asm volatile("cp.async.wait_group 0;" ::: "memory");
        }
        __syncthreads();

        int8_t* sA = sm[i & 1];
        int8_t* sB = sm[i & 1] + 8192;

        uint32_t a1f[2][4], a2f[2][4];
#pragma unroll
        for (int mt = 0; mt < 2; mt++) {
            const int r = m0 + mt * 16 + laneA_r;
            const int x = (r >> 1) & 3;
            ldsm4(a1f[mt], sA + r * 64 + ((laneA_c ^ x) << 4));
            ldsm4(a2f[mt], sA + r * 64 + (((2 | laneA_c) ^ x) << 4));
        }
#pragma unroll
        for (int np = 0; np < 4; np++) {
            const int rn = n0 + np * 16 + laneB_r;
            const int x = (rn >> 1) & 3;
            uint32_t b1f[4], b2f[4];
            ldsm4(b1f, sB + rn * 64 + ((laneB_c ^ x) << 4));
            ldsm4(b2f, sB + rn * 64 + (((2 | laneB_c) ^ x) << 4));
#pragma unroll
            for (int mt = 0; mt < 2; mt++)
#pragma unroll
                for (int j = 0; j < 2; j++) {
                    imma(acc1[mt][np * 2 + j], a1f[mt], b1f + j * 2);
                    imma(acc2[mt][np * 2 + j], a1f[mt], b2f + j * 2);
                    imma(acc2[mt][np * 2 + j], a2f[mt], b1f + j * 2);
                }
        }
        __syncthreads();
    }

    // ---------------- Epilogue ----------------
    const float i254 = 1.f / 254.f;
#pragma unroll
    for (int mt = 0; mt < 2; mt++) {
        const int gr = blockM + m0 + mt * 16 + (lane >> 2);
        const float sr0 = saP[gr], sr1 = saP[gr + 8];
#pragma unroll
        for (int nt = 0; nt < 8; nt++) {
            const int gc = blockN + n0 + nt * 8 + ((lane & 3) << 1);
            const float sc0 = sbP[gc], sc1 = sbP[gc + 1];
            const int* u = acc1[mt][nt];
            const int* w = acc2[mt][nt];
            float f0 = sr0 * sc0 * ((float)u[0] + i254 * (float)w[0]);
            float f1 = sr0 * sc1 * ((float)u[1] + i254 * (float)w[1]);
            float f2 = sr1 * sc0 * ((float)u[2] + i254 * (float)w[2]);
            float f3 = sr1 * sc1 * ((float)u[3] + i254 * (float)w[3]);
            if (bias) {
                const float b0 = bias[gc], b1 = bias[gc + 1];
                f0 += b0; f1 += b1; f2 += b0; f3 += b1;
            }
            float *p0, *p1;
            if (mode == 0) {
                p0 = C + (size_t)z * sCz + (size_t)gr * ldc + gc;
                p1 = p0 + (size_t)8 * ldc;
            } else if (mode == 1) {
                p0 = C + qkv_idx(gr, gc);
                p1 = C + qkv_idx(gr + 8, gc);
            } else {
                p0 = C + ((size_t)(z >> 3) * Tc + gr) * KH + (size_t)(z & 7) * Kc + gc;
                p1 = p0 + (size_t)8 * KH;
            }
            p0[0] = f0; p0[1] = f1;
            p1[0] = f2; p1[1] = f3;
        }
    }
}

// ---------------------------------------------------------------------------
// Per-row two-digit int8 quantization: v ~ s*(d1 + d2/254), s = rowmax/127
// ---------------------------------------------------------------------------
__global__ void quant_rows(const float* __restrict__ src,
                           int8_t* __restrict__ d1, int8_t* __restrict__ d2,
                           float* __restrict__ scale, int C, float premul)
{
    __shared__ float buf[4096];
    __shared__ float red[8];
    const size_t row = blockIdx.x;
    const float* s = src + row * (size_t)C;
    const int tid = threadIdx.x;

    float mx = 0.f;
    for (int c4 = tid * 4; c4 < C; c4 += 1024) {
        float4 v = *(const float4*)(s + c4);
        v.x *= premul; v.y *= premul; v.z *= premul; v.w *= premul;
        *(float4*)(buf + c4) = v;
        mx = fmaxf(mx, fmaxf(fmaxf(fabsf(v.x), fabsf(v.y)),
                             fmaxf(fabsf(v.z), fabsf(v.w))));
    }
#pragma unroll
    for (int o = 16; o > 0; o >>= 1)
        mx = fmaxf(mx, __shfl_xor_sync(0xffffffffu, mx, o));
    if ((tid & 31) == 0) red[tid >> 5] = mx;
    __syncthreads();
    mx = red[0];
#pragma unroll
    for (int i = 1; i < 8; i++) mx = fmaxf(mx, red[i]);

    const float rmax = fmaxf(mx, 1e-20f);
    const float sc = rmax * (1.f / 127.f);
    const float inv = 127.f / rmax;
    if (tid == 0) scale[row] = sc;

    for (int c4 = tid * 4; c4 < C; c4 += 1024) {
        const float4 v = *(const float4*)(buf + c4);
        const float vv[4] = {v.x, v.y, v.z, v.w};
        char q1[4], q2[4];
#pragma unroll
        for (int j = 0; j < 4; j++) {
            float a = rintf(vv[j] * inv);
            a = fminf(fmaxf(a, -127.f), 127.f);
            const float r = fmaf(-a, sc, vv[j]);
            float b = rintf(r * inv * 254.f);
            b = fminf(fmaxf(b, -127.f), 127.f);
            q1[j] = (char)(int)a;
            q2[j] = (char)(int)b;
        }
        *(char4*)(d1 + row * (size_t)C + c4) = make_char4(q1[0], q1[1], q1[2], q1[3]);
        *(char4*)(d2 + row * (size_t)C + c4) = make_char4(q2[0], q2[1], q2[2], q2[3]);
    }
}

// ---------------------------------------------------------------------------
// fp32 transpose [z][R][C] -> [z][C][R]
// ---------------------------------------------------------------------------
__global__ void transpose32(const float* __restrict__ src, float* __restrict__ dst,
                            int R, int C)
{
    __shared__ float t[32][33];
    const size_t zo = (size_t)blockIdx.z * R * C;
    const int c0 = blockIdx.x * 32, r0 = blockIdx.y * 32;
    const int tx = threadIdx.x, ty = threadIdx.y;
#pragma unroll
    for (int i = 0; i < 4; i++)
        t[ty + i * 8][tx] = src[zo + (size_t)(r0 + ty + i * 8) * C + c0 + tx];
    __syncthreads();
#pragma unroll
    for (int i = 0; i < 4; i++)
        dst[zo + (size_t)(c0 + ty + i * 8) * R + r0 + tx] = t[tx][ty + i * 8];
}

// ---------------------------------------------------------------------------
// Row softmax (length 2048) fused with int8 two-digit quantization.
// Quantizes w = exp(v-mx) (max 1); row scale = 1/(127*sum).
// ---------------------------------------------------------------------------
__device__ __forceinline__ uint32_t pack4i8(float a, float b, float c, float d) {
    return ((uint32_t)((int)a & 255)) | ((uint32_t)((int)b & 255) << 8)
         | ((uint32_t)((int)c & 255) << 16) | ((uint32_t)((int)d & 255) << 24);
}

__global__ void softmax_quant(const float* __restrict__ s,
                              int8_t* __restrict__ p1, int8_t* __restrict__ p2,
                              float* __restrict__ sp)
{
    __shared__ float red[8];
    const size_t base = (size_t)blockIdx.x * Tc;
    const float* p = s + base;
    const int tid = threadIdx.x;

    float v[8];
    *(float4*)&v[0] = *(const float4*)(p + tid * 8);
    *(float4*)&v[4] = *(const float4*)(p + tid * 8 + 4);

    float mx = v[0];
#pragma unroll
    for (int i = 1; i < 8; i++) mx = fmaxf(mx, v[i]);
#pragma unroll
    for (int o = 16; o > 0; o >>= 1)
        mx = fmaxf(mx, __shfl_xor_sync(0xffffffffu, mx, o));
    if ((tid & 31) == 0) red[tid >> 5] = mx;
    __syncthreads();
    mx = red[0];
#pragma unroll
    for (int i = 1; i < 8; i++) mx = fmaxf(mx, red[i]);

    float sum = 0.f;
#pragma unroll
    for (int i = 0; i < 8; i++) { v[i] = __expf(v[i] - mx); sum += v[i]; }
#pragma unroll
    for (int o = 16; o > 0; o >>= 1)
        sum += __shfl_xor_sync(0xffffffffu, sum, o);
    __syncthreads();
    if ((tid & 31) == 0) red[tid >> 5] = sum;
    __syncthreads();
    sum = 0.f;
#pragma unroll
    for (int i = 0; i < 8; i++) sum += red[i];

    if (tid == 0) sp[blockIdx.x] = (1.f / 127.f) / sum;

    float q1[8], q2[8];
#pragma unroll
    for (int i = 0; i < 8; i++) {
        float a = rintf(v[i] * 127.f);
        a = fminf(a, 127.f);
        const float r = fmaf(-a, 1.f / 127.f, v[i]);
        float b = rintf(r * (127.f * 254.f));
        b = fminf(fmaxf(b, -127.f), 127.f);
        q1[i] = a; q2[i] = b;
    }
    uint2 w1, w2;
    w1.x = pack4i8(q1[0], q1[1], q1[2], q1[3]);
    w1.y = pack4i8(q1[4], q1[5], q1[6], q1[7]);
    w2.x = pack4i8(q2[0], q2[1], q2[2], q2[3]);
    w2.y = pack4i8(q2[4], q2[5], q2[6], q2[7]);
    *(uint2*)(p1 + base + tid * 8) = w1;
    *(uint2*)(p2 + base + tid * 8) = w2;
}

// ---------------------------------------------------------------------------
// kernel_launch
// ---------------------------------------------------------------------------
#define GETSYM(var, sym) \
    { void* _p; cudaGetSymbolAddress(&_p, sym); var = decltype(var)(_p); }

extern "C" void kernel_launch(void* const* d_in, const int* in_sizes, int n_in,
                              void* d_out, int out_size)
{
    const float* x  = (const float*)d_in[0];
    const float* Wq = (const float*)d_in[1];
    const float* Wk = (const float*)d_in[2];
    const float* Wv = (const float*)d_in[3];
    const float* Wu = (const float*)d_in[4];
    const float* bu = (const float*)d_in[5];
    float* out = (float*)d_out;
    (void)in_sizes; (void)n_in; (void)out_size;

    int8_t *x1, *x2, *wq1, *wq2, *wk1, *wk2, *wv1, *wv2, *wu1, *wu2;
    int8_t *q1, *q2, *k1, *k2, *v1, *v2, *p1, *p2, *a1, *a2;
    float *sx, *swq, *swk, *swv, *swu, *sq, *sk, *sv, *sp, *satt;
    float *wT32, *tmp32, *vT32, *s32;
    GETSYM(x1, g_x1); GETSYM(x2, g_x2); GETSYM(sx, g_sx);
    GETSYM(wq1, g_wq1); GETSYM(wq2, g_wq2); GETSYM(swq, g_swq);
    GETSYM(wk1, g_wk1); GETSYM(wk2, g_wk2); GETSYM(swk, g_swk);
    GETSYM(wv1, g_wv1); GETSYM(wv2, g_wv2); GETSYM(swv, g_swv);
    GETSYM(wu1, g_wu1); GETSYM(wu2, g_wu2); GETSYM(swu, g_swu);
    GETSYM(wT32, g_wT32); GETSYM(tmp32, g_tmp32); GETSYM(vT32, g_vT32);
    GETSYM(q1, g_q1); GETSYM(q2, g_q2); GETSYM(sq, g_sq);
    GETSYM(k1, g_k1); GETSYM(k2, g_k2); GETSYM(sk, g_sk);
    GETSYM(v1, g_v1); GETSYM(v2, g_v2); GETSYM(sv, g_sv);
    GETSYM(s32, g_s32); GETSYM(p1, g_p1); GETSYM(p2, g_p2); GETSYM(sp, g_sp);
    GETSYM(a1, g_a1); GETSYM(a2, g_a2); GETSYM(satt, g_satt);

    const dim3 tb(32, 8);

    // ---- input quantization ----
    quant_rows<<<M0, 256>>>(x, x1, x2, sx, Kc, 1.f);

    transpose32<<<dim3(KH / 32, Kc / 32, 1), tb>>>(Wq, wT32, Kc, KH);
    quant_rows<<<KH, 256>>>(wT32, wq1, wq2, swq, Kc, 1.f);
    transpose32<<<dim3(KH / 32, Kc / 32, 1), tb>>>(Wk, wT32, Kc, KH);
    quant_rows<<<KH, 256>>>(wT32, wk1, wk2, swk, Kc, 1.f);
    transpose32<<<dim3(KH / 32, Kc / 32, 1), tb>>>(Wv, wT32, Kc, KH);
    quant_rows<<<KH, 256>>>(wT32, wv1, wv2, swv, Kc, 1.f);
    transpose32<<<dim3(Kc / 32, KH / 32, 1), tb>>>(Wu, wT32, KH, Kc);
    quant_rows<<<Kc, 256>>>(wT32, wu1, wu2, swu, KH, 1.f);

    // ---- stage 1: QKV projections (M=8192, N=4096, K=512) ----
    const dim3 gq(KH / 128, M0 / 128, 1);
    imma_gemm<<<gq, 256>>>(x1, x2, sx, wq1, wq2, swq, tmp32, nullptr,
                           Kc, 0, 0, 0, 0, 0, 0, 1);
    quant_rows<<<Bc * Hc * Tc, 256>>>(tmp32, q1, q2, sq, Kc, INV4);

    imma_gemm<<<gq, 256>>>(x1, x2, sx, wk1, wk2, swk, tmp32, nullptr,
                           Kc, 0, 0, 0, 0, 0, 0, 1);
    quant_rows<<<Bc * Hc * Tc, 256>>>(tmp32, k1, k2, sk, Kc, INV4);

    imma_gemm<<<gq, 256>>>(x1, x2, sx, wv1, wv2, swv, tmp32, nullptr,
                           Kc, 0, 0, 0, 0, 0, 0, 1);
    transpose32<<<dim3(Kc / 32, Tc / 32, Bc * Hc), tb>>>(tmp32, vT32, Tc, Kc);
    quant_rows<<<Bc * Hc * Kc, 256>>>(vT32, v1, v2, sv, Tc, 1.f);

    // ---- stage 2: scores (M=N=2048, K=512, z=32) ----
    imma_gemm<<<dim3(Tc / 128, Tc / 128, Bc * Hc), 256>>>(
        q1, q2, sq, k1, k2, sk, s32, nullptr,
        Kc, Tc, (size_t)Tc * Kc, (size_t)Tc * Kc, (size_t)Tc * Tc, Tc, Tc, 0);

    // ---- stage 3: softmax + quant ----
    softmax_quant<<<Bc * Hc * Tc, 256>>>(s32, p1, p2, sp);

    // ---- stage 4: PV (M=2048, N=512, K=2048, z=32) -> att layout ----
    imma_gemm<<<dim3(Kc / 128, Tc / 128, Bc * Hc), 256>>>(
        p1, p2, sp, v1, v2, sv, tmp32, nullptr,
        Tc, 0, (size_t)Tc * Tc, (size_t)Kc * Tc, 0, Tc, Kc, 2);

    // ---- quantize att (rows of 4096) ----
    quant_rows<<<M0, 256>>>(tmp32, a1, a2, satt, KH, 1.f);

    // ---- stage 5: output projection + bias (M=8192, N=512, K=4096) ----
    imma_gemm<<<dim3(Kc / 128, M0 / 128, 1), 256>>>(
        a1, a2, satt, wu1, wu2, swu, out, bu,
        KH, Kc, 0, 0, 0, 0, 0, 0);
}

// round 16
// speedup vs baseline: 3.0072x; 3.0072x over previous
#include <cuda_runtime.h>
#include <cuda_bf16.h>
#include <cstdint>

// ---------------------------------------------------------------------------
// Problem constants
// ---------------------------------------------------------------------------
#define Bc 4
#define Hc 8
#define Tc 2048
#define Kc 512
#define KH 4096
#define M0 8192
#define INV4 0.2102241038134287f   // 512^(-0.25)

#define NA   ((size_t)M0 * Kc)
#define NW   ((size_t)Kc * KH)
#define NQ   ((size_t)Bc * Hc * Tc * Kc)
#define NS   ((size_t)Bc * Hc * Tc * Tc)
#define NATT ((size_t)M0 * KH)

// ---------------------------------------------------------------------------
// Static device scratch
// ---------------------------------------------------------------------------
__device__ __align__(16) __nv_bfloat16 g_xh[NA],  g_xl[NA];
__device__ __align__(16) __nv_bfloat16 g_WqTh[NW], g_WqTl[NW];
__device__ __align__(16) __nv_bfloat16 g_WkTh[NW], g_WkTl[NW];
__device__ __align__(16) __nv_bfloat16 g_WvTh[NW], g_WvTl[NW];
__device__ __align__(16) __nv_bfloat16 g_WuTh[NW], g_WuTl[NW];
__device__ __align__(16) __nv_bfloat16 g_qh[NQ], g_ql[NQ], g_kh[NQ], g_kl[NQ];
__device__ float g_v32[NQ];
__device__ __align__(16) __nv_bfloat16 g_vTh[NQ], g_vTl[NQ];
__device__ float g_s32[NS];
__device__ __align__(16) __nv_bfloat16 g_ph[NS], g_pl[NS];
__device__ __align__(16) __nv_bfloat16 g_atth[NATT], g_attl[NATT];

// ---------------------------------------------------------------------------
// PTX helpers
// ---------------------------------------------------------------------------
__device__ __forceinline__ void cpa16(const void* smemPtr, const void* gptr) {
    uint32_t s = (uint32_t)__cvta_generic_to_shared(smemPtr);
    asm volatile("cp.async.cg.shared.global [%0], [%1], 16;" :: "r"(s), "l"(gptr));
}

__device__ __forceinline__ void ldsm4(uint32_t* d, const __nv_bfloat16* p) {
    uint32_t a = (uint32_t)__cvta_generic_to_shared(p);
    asm volatile("ldmatrix.sync.aligned.m8n8.x4.shared.b16 {%0,%1,%2,%3}, [%4];"
                 : "=r"(d[0]), "=r"(d[1]), "=r"(d[2]), "=r"(d[3]) : "r"(a));
}

__device__ __forceinline__ void mma16816(float* c, const uint32_t* a, const uint32_t* b) {
    asm volatile(
        "mma.sync.aligned.m16n8k16.row.col.f32.bf16.bf16.f32 "
        "{%0,%1,%2,%3}, {%4,%5,%6,%7}, {%8,%9}, {%0,%1,%2,%3};"
        : "+f"(c[0]), "+f"(c[1]), "+f"(c[2]), "+f"(c[3])
        : "r"(a[0]), "r"(a[1]), "r"(a[2]), "r"(a[3]), "r"(b[0]), "r"(b[1]));
}

// Swizzled smem offset (bf16 elements): tile row r, 8-elem chunk kc (0..3).
__device__ __forceinline__ int sw_off(int r, int kc) {
    return r * 32 + ((kc ^ ((r >> 1) & 3)) << 3);
}

// qkv layout index: row m = b*2048+t, col c = h*512+k  ->  [b,h,t,k]
__device__ __forceinline__ size_t qkv_idx(int m, int c) {
    return ((size_t)((m >> 11) * 8 + (c >> 9))) * ((size_t)Tc * Kc)
         + (size_t)(m & (Tc - 1)) * Kc + (c & (Kc - 1));
}

// ---------------------------------------------------------------------------
// 3-pass split-bf16 MMA GEMM (R4 core).  C = A * B^T per z-batch.
// A: [M][Kdim] k-contig (hi,lo); B: [N][Kdim] k-contig (hi,lo).
// CTA tile 128x128, BK=32, 8 warps of 32(M)x64(N), double-buffered cp.async.
// Output (cmode): 0 = linear  C + z*sCz + r*ldc + c
//                 1 = qkv layout [b,h,t,k]
//                 2 = att layout [b,t,h*512+k] (z = b*8+h)
// If Ch != nullptr: write (hi,lo) bf16 split of (val*scale) instead of fp32.
// ---------------------------------------------------------------------------
__device__ __forceinline__ void load_tiles(
    __nv_bfloat16* s,
    const __nv_bfloat16* gAh, const __nv_bfloat16* gAl,
    const __nv_bfloat16* gBh, const __nv_bfloat16* gBl,
    int Kdim, int k0, int tid)
{
#pragma unroll
    for (int i = 0; i < 2; i++) {
        int c = tid + (i << 8);          // 0..511
        int r = c >> 2, kc = c & 3;
        int so = sw_off(r, kc);
        size_t go = (size_t)r * Kdim + k0 + (kc << 3);
        cpa16(s + so,         gAh + go);
        cpa16(s + 4096 + so,  gAl + go);
        cpa16(s + 8192 + so,  gBh + go);
        cpa16(s + 12288 + so, gBl + go);
    }
    asm volatile("cp.async.commit_group;" ::: "memory");
}

__device__ __forceinline__ void compute_tiles(
    const __nv_bfloat16* sb, float (&acc)[2][8][4],
    int m0, int n0, int lane)
{
    const __nv_bfloat16* sAh = sb;
    const __nv_bfloat16* sAl = sb + 4096;
    const __nv_bfloat16* sBh = sb + 8192;
    const __nv_bfloat16* sBl = sb + 12288;

    const int laneA_r = lane & 15;
    const int laneA_c = lane >> 4;
    const int laneB_r = (lane & 7) | ((lane >> 1) & 8);
    const int laneB_c = (lane >> 3) & 1;

#pragma unroll
    for (int ks8 = 0; ks8 < 4; ks8 += 2) {     // two k16 steps per BK32
        uint32_t aH[2][4], aL[2][4];
#pragma unroll
        for (int mt = 0; mt < 2; mt++) {
            int r = m0 + mt * 16 + laneA_r;
            int so = sw_off(r, ks8 + laneA_c);
            ldsm4(aH[mt], sAh + so);
            ldsm4(aL[mt], sAl + so);
        }
#pragma unroll
        for (int np = 0; np < 4; np++) {
            int r = n0 + np * 16 + laneB_r;
            int so = sw_off(r, ks8 + laneB_c);
            uint32_t bH[4], bL[4];
            ldsm4(bH, sBh + so);
            ldsm4(bL, sBl + so);
#pragma unroll
            for (int mt = 0; mt < 2; mt++)
#pragma unroll
                for (int j = 0; j < 2; j++)
                    mma16816(acc[mt][np * 2 + j], aH[mt], bH + j * 2);
#pragma unroll
            for (int mt = 0; mt < 2; mt++)
#pragma unroll
                for (int j = 0; j < 2; j++)
                    mma16816(acc[mt][np * 2 + j], aH[mt], bL + j * 2);
#pragma unroll
            for (int mt = 0; mt < 2; mt++)
#pragma unroll
                for (int j = 0; j < 2; j++)
                    mma16816(acc[mt][np * 2 + j], aL[mt], bH + j * 2);
        }
    }
}

__global__ __launch_bounds__(256, 2)
void mma_gemm(const __nv_bfloat16* __restrict__ Ah, const __nv_bfloat16* __restrict__ Al,
              const __nv_bfloat16* __restrict__ Bh, const __nv_bfloat16* __restrict__ Bl,
              float* __restrict__ C,
              __nv_bfloat16* __restrict__ Ch, __nv_bfloat16* __restrict__ Cl,
              const float* __restrict__ bias,
              int Kdim, int ldc,
              size_t strideAz, size_t strideBz, size_t strideCz,
              int cmode, float scale)
{
    extern __shared__ __nv_bfloat16 smem[];   // 2 bufs x 16384 bf16 = 64KB

    const int tid = threadIdx.x;
    const int lane = tid & 31, warp = tid >> 5;
    const int z = blockIdx.z;
    const int blockM = blockIdx.y * 128, blockN = blockIdx.x * 128;
    const int m0 = (warp >> 1) * 32, n0 = (warp & 1) * 64;

    const __nv_bfloat16* gAh = Ah + (size_t)z * strideAz + (size_t)blockM * Kdim;
    const __nv_bfloat16* gAl = Al + (size_t)z * strideAz + (size_t)blockM * Kdim;
    const __nv_bfloat16* gBh = Bh + (size_t)z * strideBz + (size_t)blockN * Kdim;
    const __nv_bfloat16* gBl = Bl + (size_t)z * strideBz + (size_t)blockN * Kdim;

    float acc[2][8][4];
#pragma unroll
    for (int a = 0; a < 2; a++)
#pragma unroll
        for (int b = 0; b < 8; b++)
#pragma unroll
            for (int c = 0; c < 4; c++) acc[a][b][c] = 0.f;

    const int nk = Kdim >> 5;
    load_tiles(smem, gAh, gAl, gBh, gBl, Kdim, 0, tid);

    for (int i = 0; i < nk; i++) {
        if (i + 1 < nk) {
            load_tiles(smem + ((i + 1) & 1) * 16384, gAh, gAl, gBh, gBl,
                       Kdim, (i + 1) << 5, tid);
            asm volatile("cp.async.wait_group 1;" ::: "memory");
        } else {
            asm volatile("cp.async.wait_group 0;" ::: "memory");
        }
        __syncthreads();
        compute_tiles(smem + (i & 1) * 16384, acc, m0, n0, lane);
        __syncthreads();
    }

    // ------------------------- Epilogue -------------------------
#pragma unroll
    for (int mt = 0; mt < 2; mt++)
#pragma unroll
        for (int nt = 0; nt < 8; nt++) {
            const int gr = blockM + m0 + mt * 16 + (lane >> 2);
            const int gc = blockN + n0 + nt * 8 + ((lane & 3) << 1);
            float c0 = acc[mt][nt][0], c1 = acc[mt][nt][1];
            float c2 = acc[mt][nt][2], c3 = acc[mt][nt][3];
            if (bias) {
                const float b0 = bias[gc], b1 = bias[gc + 1];
                c0 += b0; c1 += b1; c2 += b0; c3 += b1;
            }

            size_t i0, i1;
            if (cmode == 0) {
                i0 = (size_t)z * strideCz + (size_t)gr * ldc + gc;
                i1 = i0 + (size_t)8 * ldc;
            } else if (cmode == 1) {
                i0 = qkv_idx(gr, gc);
                i1 = qkv_idx(gr + 8, gc);
            } else {
                i0 = ((size_t)(z >> 3) * Tc + gr) * KH + (size_t)(z & 7) * Kc + gc;
                i1 = i0 + (size_t)8 * KH;
            }

            if (Ch) {
                c0 *= scale; c1 *= scale; c2 *= scale; c3 *= scale;
                __nv_bfloat162 h0 = __floats2bfloat162_rn(c0, c1);
                __nv_bfloat162 h1 = __floats2bfloat162_rn(c2, c3);
                __nv_bfloat162 l0 = __floats2bfloat162_rn(
                    c0 - __low2float(h0), c1 - __high2float(h0));
                __nv_bfloat162 l1 = __floats2bfloat162_rn(
                    c2 - __low2float(h1), c3 - __high2float(h1));
                *(__nv_bfloat162*)(Ch + i0) = h0;
                *(__nv_bfloat162*)(Ch + i1) = h1;
                *(__nv_bfloat162*)(Cl + i0) = l0;
                *(__nv_bfloat162*)(Cl + i1) = l1;
            } else {
                C[i0] = c0; C[i0 + 1] = c1;
                C[i1] = c2; C[i1 + 1] = c3;
            }
        }
}

// ---------------------------------------------------------------------------
// fp32 -> (hi, lo) bf16 split, elementwise
// ---------------------------------------------------------------------------
__global__ void split_kernel(const float* __restrict__ src,
                             __nv_bfloat16* __restrict__ hi,
                             __nv_bfloat16* __restrict__ lo,
                             float scale, int n4)
{
    int i = blockIdx.x * blockDim.x + threadIdx.x;
    if (i >= n4) return;
    float4 v = ((const float4*)src)[i];
    float f[4] = {v.x * scale, v.y * scale, v.z * scale, v.w * scale};
    __nv_bfloat16 h[4], l[4];
#pragma unroll
    for (int j = 0; j < 4; j++) {
        h[j] = __float2bfloat16(f[j]);
        l[j] = __float2bfloat16(f[j] - __bfloat162float(h[j]));
    }
    ((__nv_bfloat162*)hi)[2 * i]     = __nv_bfloat162(h[0], h[1]);
    ((__nv_bfloat162*)hi)[2 * i + 1] = __nv_bfloat162(h[2], h[3]);
    ((__nv_bfloat162*)lo)[2 * i]     = __nv_bfloat162(l[0], l[1]);
    ((__nv_bfloat162*)lo)[2 * i + 1] = __nv_bfloat162(l[2], l[3]);
}

// ---------------------------------------------------------------------------
// fp32 [R][C] -> transposed (hi, lo) bf16 [C][R], batched over z
// ---------------------------------------------------------------------------
__global__ void tsplit_kernel(const float* __restrict__ src,
                              __nv_bfloat16* __restrict__ hi,
                              __nv_bfloat16* __restrict__ lo,
                              int R, int C)
{
    __shared__ float t[32][33];
    size_t zoff = (size_t)blockIdx.z * R * C;
    const float* s = src + zoff;
    __nv_bfloat16* ho = hi + zoff;
    __nv_bfloat16* lor = lo + zoff;
    int c0 = blockIdx.x * 32, r0 = blockIdx.y * 32;

#pragma unroll
    for (int i = 0; i < 4; i++) {
        int r = r0 + threadIdx.y + i * 8;
        t[threadIdx.y + i * 8][threadIdx.x] = s[(size_t)r * C + c0 + threadIdx.x];
    }
    __syncthreads();
#pragma unroll
    for (int i = 0; i < 4; i++) {
        int cc = c0 + threadIdx.y + i * 8;
        int rr = r0 + threadIdx.x;
        float v = t[threadIdx.x][threadIdx.y + i * 8];
        __nv_bfloat16 h = __float2bfloat16(v);
        ho[(size_t)cc * R + rr] = h;
        lor[(size_t)cc * R + rr] = __float2bfloat16(v - __bfloat162float(h));
    }
}

// ---------------------------------------------------------------------------
// Row softmax (length 2048) with (hi, lo) bf16 output
// ---------------------------------------------------------------------------
__global__ void softmax_split_kernel(const float* __restrict__ s,
                                     __nv_bfloat16* __restrict__ ph,
                                     __nv_bfloat16* __restrict__ pl)
{
    __shared__ float red[8];
    const size_t base = (size_t)blockIdx.x * Tc;
    const float* p = s + base;
    const int tid = threadIdx.x;

    float v[8];
    *(float4*)&v[0] = *(const float4*)(p + tid * 8);
    *(float4*)&v[4] = *(const float4*)(p + tid * 8 + 4);

    float mx = v[0];
#pragma unroll
    for (int i = 1; i < 8; i++) mx = fmaxf(mx, v[i]);
#pragma unroll
    for (int o = 16; o > 0; o >>= 1)
        mx = fmaxf(mx, __shfl_xor_sync(0xffffffffu, mx, o));
    if ((tid & 31) == 0) red[tid >> 5] = mx;
    __syncthreads();
    mx = red[0];
#pragma unroll
    for (int i = 1; i < 8; i++) mx = fmaxf(mx, red[i]);

    float sum = 0.f;
#pragma unroll
    for (int i = 0; i < 8; i++) { v[i] = __expf(v[i] - mx); sum += v[i]; }
#pragma unroll
    for (int o = 16; o > 0; o >>= 1)
        sum += __shfl_xor_sync(0xffffffffu, sum, o);
    __syncthreads();
    if ((tid & 31) == 0) red[tid >> 5] = sum;
    __syncthreads();
    sum = 0.f;
#pragma unroll
    for (int i = 0; i < 8; i++) sum += red[i];
    const float inv = 1.f / sum;

    __nv_bfloat16 h[8], l[8];
#pragma unroll
    for (int i = 0; i < 8; i++) {
        float q = v[i] * inv;
        h[i] = __float2bfloat16(q);
        l[i] = __float2bfloat16(q - __bfloat162float(h[i]));
    }
#pragma unroll
    for (int i = 0; i < 4; i++) {
        ((__nv_bfloat162*)(ph + base))[tid * 4 + i] = __nv_bfloat162(h[2*i], h[2*i+1]);
        ((__nv_bfloat162*)(pl + base))[tid * 4 + i] = __nv_bfloat162(l[2*i], l[2*i+1]);
    }
}

// ---------------------------------------------------------------------------
// kernel_launch
// ---------------------------------------------------------------------------
#define GETSYM(var, sym) \
    { void* _p; cudaGetSymbolAddress(&_p, sym); var = decltype(var)(_p); }

extern "C" void kernel_launch(void* const* d_in, const int* in_sizes, int n_in,
                              void* d_out, int out_size)
{
    const float* x  = (const float*)d_in[0];
    const float* Wq = (const float*)d_in[1];
    const float* Wk = (const float*)d_in[2];
    const float* Wv = (const float*)d_in[3];
    const float* Wu = (const float*)d_in[4];
    const float* bu = (const float*)d_in[5];
    float* out = (float*)d_out;
    (void)in_sizes; (void)n_in; (void)out_size;

    cudaFuncSetAttribute(mma_gemm, cudaFuncAttributeMaxDynamicSharedMemorySize, 65536);

    __nv_bfloat16 *xh, *xl, *WqTh, *WqTl, *WkTh, *WkTl, *WvTh, *WvTl, *WuTh, *WuTl;
    __nv_bfloat16 *qh, *ql, *kh, *kl, *vTh, *vTl, *ph, *pl, *atth, *attl;
    float *v32, *s32;
    GETSYM(xh, g_xh); GETSYM(xl, g_xl);
    GETSYM(WqTh, g_WqTh); GETSYM(WqTl, g_WqTl);
    GETSYM(WkTh, g_WkTh); GETSYM(WkTl, g_WkTl);
    GETSYM(WvTh, g_WvTh); GETSYM(WvTl, g_WvTl);
    GETSYM(WuTh, g_WuTh); GETSYM(WuTl, g_WuTl);
    GETSYM(qh, g_qh); GETSYM(ql, g_ql); GETSYM(kh, g_kh); GETSYM(kl, g_kl);
    GETSYM(v32, g_v32); GETSYM(vTh, g_vTh); GETSYM(vTl, g_vTl);
    GETSYM(s32, g_s32); GETSYM(ph, g_ph); GETSYM(pl, g_pl);
    GETSYM(atth, g_atth); GETSYM(attl, g_attl);

    const dim3 tb(32, 8);

    // ---- input conversions ----
    split_kernel<<<(int)(NA / 4 / 256), 256>>>(x, xh, xl, 1.f, (int)(NA / 4));
    tsplit_kernel<<<dim3(KH / 32, Kc / 32, 1), tb>>>(Wq, WqTh, WqTl, Kc, KH);
    tsplit_kernel<<<dim3(KH / 32, Kc / 32, 1), tb>>>(Wk, WkTh, WkTl, Kc, KH);
    tsplit_kernel<<<dim3(KH / 32, Kc / 32, 1), tb>>>(Wv, WvTh, WvTl, Kc, KH);
    tsplit_kernel<<<dim3(Kc / 32, KH / 32, 1), tb>>>(Wu, WuTh, WuTl, KH, Kc);

    // ---- stage 1: QKV projections (M=8192, N=4096, K=512) ----
    // Q, K: fused split epilogue (scaled), directly to [b,h,t,k] hi/lo.
    const dim3 gq(KH / 128, M0 / 128, 1);
    mma_gemm<<<gq, 256, 65536>>>(xh, xl, WqTh, WqTl, nullptr, qh, ql, nullptr,
                                 Kc, 0, 0, 0, 0, 1, INV4);
    mma_gemm<<<gq, 256, 65536>>>(xh, xl, WkTh, WkTl, nullptr, kh, kl, nullptr,
                                 Kc, 0, 0, 0, 0, 1, INV4);
    // V: fp32 to qkv layout, then per-head transpose+split.
    mma_gemm<<<gq, 256, 65536>>>(xh, xl, WvTh, WvTl, v32, nullptr, nullptr, nullptr,
                                 Kc, 0, 0, 0, 0, 1, 1.f);
    tsplit_kernel<<<dim3(Kc / 32, Tc / 32, Bc * Hc), tb>>>(v32, vTh, vTl, Tc, Kc);

    // ---- stage 2: scores (M=N=2048, K=512, z=32) -> fp32 ----
    mma_gemm<<<dim3(Tc / 128, Tc / 128, Bc * Hc), 256, 65536>>>(
        qh, ql, kh, kl, s32, nullptr, nullptr, nullptr,
        Kc, Tc, (size_t)Tc * Kc, (size_t)Tc * Kc, (size_t)Tc * Tc, 0, 1.f);

    // ---- stage 3: softmax -> split probs ----
    softmax_split_kernel<<<Bc * Hc * Tc, 256>>>(s32, ph, pl);

    // ---- stage 4: PV (M=2048, N=512, K=2048, z=32): fused split to att layout ----
    mma_gemm<<<dim3(Kc / 128, Tc / 128, Bc * Hc), 256, 65536>>>(
        ph, pl, vTh, vTl, nullptr, atth, attl, nullptr,
        Tc, 0, (size_t)Tc * Tc, (size_t)Kc * Tc, 0, 2, 1.f);

    // ---- stage 5: output projection + bias (M=8192, N=512, K=4096) ----
    mma_gemm<<<dim3(Kc / 128, M0 / 128, 1), 256, 65536>>>(
        atth, attl, WuTh, WuTl, out, nullptr, nullptr, bu,
        KH, Kc, 0, 0, 0, 0, 1.f);
}

// round 17
// speedup vs baseline: 3.2151x; 1.0691x over previous
#include <cuda_runtime.h>
#include <cuda_bf16.h>
#include <cstdint>

// ---------------------------------------------------------------------------
// Problem constants
// ---------------------------------------------------------------------------
#define Bc 4
#define Hc 8
#define Tc 2048
#define Kc 512
#define KH 4096
#define M0 8192
#define INV4 0.2102241038134287f   // 512^(-0.25)

#define NA   ((size_t)M0 * Kc)
#define NW   ((size_t)Kc * KH)
#define NQ   ((size_t)Bc * Hc * Tc * Kc)
#define NS   ((size_t)Bc * Hc * Tc * Tc)
#define NATT ((size_t)M0 * KH)

// ---------------------------------------------------------------------------
// Static device scratch
// ---------------------------------------------------------------------------
__device__ __align__(16) __nv_bfloat16 g_xh[NA],  g_xl[NA];
__device__ __align__(16) __nv_bfloat16 g_WqTh[NW], g_WqTl[NW];
__device__ __align__(16) __nv_bfloat16 g_WkTh[NW], g_WkTl[NW];
__device__ __align__(16) __nv_bfloat16 g_WvTh[NW], g_WvTl[NW];
__device__ __align__(16) __nv_bfloat16 g_WuTh[NW], g_WuTl[NW];
__device__ __align__(16) __nv_bfloat16 g_qh[NQ], g_ql[NQ], g_kh[NQ], g_kl[NQ];
__device__ float g_v32[NQ];
__device__ __align__(16) __nv_bfloat16 g_vTh[NQ], g_vTl[NQ];
__device__ __align__(16) __nv_bfloat16 g_eh[NS], g_el[NS];   // exp(scores) hi/lo
__device__ __align__(16) __nv_bfloat16 g_atth[NATT], g_attl[NATT];

// ---------------------------------------------------------------------------
// PTX helpers
// ---------------------------------------------------------------------------
__device__ __forceinline__ void cpa16(const void* smemPtr, const void* gptr) {
    uint32_t s = (uint32_t)__cvta_generic_to_shared(smemPtr);
    asm volatile("cp.async.cg.shared.global [%0], [%1], 16;" :: "r"(s), "l"(gptr));
}

__device__ __forceinline__ void ldsm4(uint32_t* d, const __nv_bfloat16* p) {
    uint32_t a = (uint32_t)__cvta_generic_to_shared(p);
    asm volatile("ldmatrix.sync.aligned.m8n8.x4.shared.b16 {%0,%1,%2,%3}, [%4];"
                 : "=r"(d[0]), "=r"(d[1]), "=r"(d[2]), "=r"(d[3]) : "r"(a));
}

__device__ __forceinline__ void mma16816(float* c, const uint32_t* a, const uint32_t* b) {
    asm volatile(
        "mma.sync.aligned.m16n8k16.row.col.f32.bf16.bf16.f32 "
        "{%0,%1,%2,%3}, {%4,%5,%6,%7}, {%8,%9}, {%0,%1,%2,%3};"
        : "+f"(c[0]), "+f"(c[1]), "+f"(c[2]), "+f"(c[3])
        : "r"(a[0]), "r"(a[1]), "r"(a[2]), "r"(a[3]), "r"(b[0]), "r"(b[1]));
}

// Swizzled smem offset (bf16 elements): tile row r, 8-elem chunk kc (0..3).
__device__ __forceinline__ int sw_off(int r, int kc) {
    return r * 32 + ((kc ^ ((r >> 1) & 3)) << 3);
}

// qkv layout index: row m = b*2048+t, col c = h*512+k  ->  [b,h,t,k]
__device__ __forceinline__ size_t qkv_idx(int m, int c) {
    return ((size_t)((m >> 11) * 8 + (c >> 9))) * ((size_t)Tc * Kc)
         + (size_t)(m & (Tc - 1)) * Kc + (c & (Kc - 1));
}

__device__ __forceinline__ void split_store(__nv_bfloat16* Ch, __nv_bfloat16* Cl,
                                            size_t i0, size_t i1,
                                            float c0, float c1, float c2, float c3) {
    __nv_bfloat162 h0 = __floats2bfloat162_rn(c0, c1);
    __nv_bfloat162 h1 = __floats2bfloat162_rn(c2, c3);
    __nv_bfloat162 l0 = __floats2bfloat162_rn(c0 - __low2float(h0), c1 - __high2float(h0));
    __nv_bfloat162 l1 = __floats2bfloat162_rn(c2 - __low2float(h1), c3 - __high2float(h1));
    *(__nv_bfloat162*)(Ch + i0) = h0;
    *(__nv_bfloat162*)(Ch + i1) = h1;
    *(__nv_bfloat162*)(Cl + i0) = l0;
    *(__nv_bfloat162*)(Cl + i1) = l1;
}

// ---------------------------------------------------------------------------
// Shared GEMM machinery: 128x128 CTA tile, BK=32, 8 warps of 32(M)x64(N),
// 3-pass split-bf16 (Ah*Bh + Ah*Bl + Al*Bh), double-buffered cp.async.
// ---------------------------------------------------------------------------
__device__ __forceinline__ void load_tiles(
    __nv_bfloat16* s,
    const __nv_bfloat16* gAh, const __nv_bfloat16* gAl,
    const __nv_bfloat16* gBh, const __nv_bfloat16* gBl,
    int Kdim, int k0, int tid)
{
#pragma unroll
    for (int i = 0; i < 2; i++) {
        int c = tid + (i << 8);          // 0..511
        int r = c >> 2, kc = c & 3;
        int so = sw_off(r, kc);
        size_t go = (size_t)r * Kdim + k0 + (kc << 3);
        cpa16(s + so,         gAh + go);
        cpa16(s + 4096 + so,  gAl + go);
        cpa16(s + 8192 + so,  gBh + go);
        cpa16(s + 12288 + so, gBl + go);
    }
    asm volatile("cp.async.commit_group;" ::: "memory");
}

template <bool DO_SUM>
__device__ __forceinline__ void compute_tiles(
    const __nv_bfloat16* sb, float (&acc)[2][8][4], float (&accS)[2][4],
    int m0, int n0, int lane)
{
    const __nv_bfloat16* sAh = sb;
    const __nv_bfloat16* sAl = sb + 4096;
    const __nv_bfloat16* sBh = sb + 8192;
    const __nv_bfloat16* sBl = sb + 12288;

    const int laneA_r = lane & 15;
    const int laneA_c = lane >> 4;
    const int laneB_r = (lane & 7) | ((lane >> 1) & 8);
    const int laneB_c = (lane >> 3) & 1;

    const uint32_t ones2[2] = {0x3F803F80u, 0x3F803F80u};   // bf16 1.0 pair

#pragma unroll
    for (int ks8 = 0; ks8 < 4; ks8 += 2) {     // two k16 steps per BK32
        uint32_t aH[2][4], aL[2][4];
#pragma unroll
        for (int mt = 0; mt < 2; mt++) {
            int r = m0 + mt * 16 + laneA_r;
            int so = sw_off(r, ks8 + laneA_c);
            ldsm4(aH[mt], sAh + so);
            ldsm4(aL[mt], sAl + so);
        }
        if (DO_SUM) {   // row sums of A (hi+lo) via ones-MMA; no ldsm needed
            mma16816(accS[0], aH[0], ones2);
            mma16816(accS[0], aL[0], ones2);
            mma16816(accS[1], aH[1], ones2);
            mma16816(accS[1], aL[1], ones2);
        }
#pragma unroll
        for (int np = 0; np < 4; np++) {
            int r = n0 + np * 16 + laneB_r;
            int so = sw_off(r, ks8 + laneB_c);
            uint32_t bH[4], bL[4];
            ldsm4(bH, sBh + so);
            ldsm4(bL, sBl + so);
#pragma unroll
            for (int mt = 0; mt < 2; mt++)
#pragma unroll
                for (int j = 0; j < 2; j++)
                    mma16816(acc[mt][np * 2 + j], aH[mt], bH + j * 2);
#pragma unroll
            for (int mt = 0; mt < 2; mt++)
#pragma unroll
                for (int j = 0; j < 2; j++)
                    mma16816(acc[mt][np * 2 + j], aH[mt], bL + j * 2);
#pragma unroll
            for (int mt = 0; mt < 2; mt++)
#pragma unroll
                for (int j = 0; j < 2; j++)
                    mma16816(acc[mt][np * 2 + j], aL[mt], bH + j * 2);
        }
    }
}

// ---------------------------------------------------------------------------
// Generic GEMM.  C = A * B^T per z-batch.
// cmode: 0 = fp32/split linear  C + z*sCz + r*ldc + c  (+bias)
//        1 = qkv layout [b,h,t,k]
//        2 = att layout [b,t,h*512+k] with rowsum normalization (DO_SUM)
//        3 = linear layout, val -> exp(val), split output
// If Ch != nullptr: write (hi,lo) bf16 split of (val*scale); else fp32 to C.
// ---------------------------------------------------------------------------
template <bool DO_SUM>
__global__ __launch_bounds__(256, 2)
void mma_gemm(const __nv_bfloat16* __restrict__ Ah, const __nv_bfloat16* __restrict__ Al,
              const __nv_bfloat16* __restrict__ Bh, const __nv_bfloat16* __restrict__ Bl,
              float* __restrict__ C,
              __nv_bfloat16* __restrict__ Ch, __nv_bfloat16* __restrict__ Cl,
              const float* __restrict__ bias,
              int Kdim, int ldc,
              size_t strideAz, size_t strideBz, size_t strideCz,
              int cmode, float scale)
{
    extern __shared__ __nv_bfloat16 smem[];   // 2 bufs x 16384 bf16 = 64KB

    const int tid = threadIdx.x;
    const int lane = tid & 31, warp = tid >> 5;
    const int z = blockIdx.z;
    const int blockM = blockIdx.y * 128, blockN = blockIdx.x * 128;
    const int m0 = (warp >> 1) * 32, n0 = (warp & 1) * 64;

    const __nv_bfloat16* gAh = Ah + (size_t)z * strideAz + (size_t)blockM * Kdim;
    const __nv_bfloat16* gAl = Al + (size_t)z * strideAz + (size_t)blockM * Kdim;
    const __nv_bfloat16* gBh = Bh + (size_t)z * strideBz + (size_t)blockN * Kdim;
    const __nv_bfloat16* gBl = Bl + (size_t)z * strideBz + (size_t)blockN * Kdim;

    float acc[2][8][4];
    float accS[2][4];
#pragma unroll
    for (int a = 0; a < 2; a++) {
#pragma unroll
        for (int b = 0; b < 8; b++)
#pragma unroll
            for (int c = 0; c < 4; c++) acc[a][b][c] = 0.f;
#pragma unroll
        for (int c = 0; c < 4; c++) accS[a][c] = 0.f;
    }

    const int nk = Kdim >> 5;
    load_tiles(smem, gAh, gAl, gBh, gBl, Kdim, 0, tid);

    for (int i = 0; i < nk; i++) {
        if (i + 1 < nk) {
            load_tiles(smem + ((i + 1) & 1) * 16384, gAh, gAl, gBh, gBl,
                       Kdim, (i + 1) << 5, tid);
            asm volatile("cp.async.wait_group 1;" ::: "memory");
        } else {
            asm volatile("cp.async.wait_group 0;" ::: "memory");
        }
        __syncthreads();
        compute_tiles<DO_SUM>(smem + (i & 1) * 16384, acc, accS, m0, n0, lane);
        __syncthreads();
    }

    // ------------------------- Epilogue -------------------------
#pragma unroll
    for (int mt = 0; mt < 2; mt++) {
        float inv0 = 1.f, inv1 = 1.f;
        if (DO_SUM) { inv0 = 1.f / accS[mt][0]; inv1 = 1.f / accS[mt][2]; }
#pragma unroll
        for (int nt = 0; nt < 8; nt++) {
            const int gr = blockM + m0 + mt * 16 + (lane >> 2);
            const int gc = blockN + n0 + nt * 8 + ((lane & 3) << 1);
            float c0 = acc[mt][nt][0], c1 = acc[mt][nt][1];
            float c2 = acc[mt][nt][2], c3 = acc[mt][nt][3];
            if (bias) {
                const float b0 = bias[gc], b1 = bias[gc + 1];
                c0 += b0; c1 += b1; c2 += b0; c3 += b1;
            }
            if (DO_SUM) { c0 *= inv0; c1 *= inv0; c2 *= inv1; c3 *= inv1; }
            if (cmode == 3) {
                c0 = __expf(c0); c1 = __expf(c1);
                c2 = __expf(c2); c3 = __expf(c3);
            }

            size_t i0, i1;
            if (cmode == 1) {
                i0 = qkv_idx(gr, gc);
                i1 = qkv_idx(gr + 8, gc);
            } else if (cmode == 2) {
                i0 = ((size_t)(z >> 3) * Tc + gr) * KH + (size_t)(z & 7) * Kc + gc;
                i1 = i0 + (size_t)8 * KH;
            } else {
                i0 = (size_t)z * strideCz + (size_t)gr * ldc + gc;
                i1 = i0 + (size_t)8 * ldc;
            }

            if (Ch) {
                c0 *= scale; c1 *= scale; c2 *= scale; c3 *= scale;
                split_store(Ch, Cl, i0, i1, c0, c1, c2, c3);
            } else {
                C[i0] = c0; C[i0 + 1] = c1;
                C[i1] = c2; C[i1 + 1] = c3;
            }
        }
    }
}

// ---------------------------------------------------------------------------
// Merged QKV projection GEMM: z=0 Q (split, INV4), z=1 K (split, INV4),
// z=2 V (fp32).  All outputs in qkv layout [b,h,t,k].
// ---------------------------------------------------------------------------
__global__ __launch_bounds__(256, 2)
void qkv_gemm(const __nv_bfloat16* __restrict__ xh, const __nv_bfloat16* __restrict__ xl,
              const __nv_bfloat16* __restrict__ Wqh, const __nv_bfloat16* __restrict__ Wql,
              const __nv_bfloat16* __restrict__ Wkh, const __nv_bfloat16* __restrict__ Wkl,
              const __nv_bfloat16* __restrict__ Wvh, const __nv_bfloat16* __restrict__ Wvl,
              __nv_bfloat16* __restrict__ qh, __nv_bfloat16* __restrict__ ql,
              __nv_bfloat16* __restrict__ kh, __nv_bfloat16* __restrict__ kl,
              float* __restrict__ v32)
{
    extern __shared__ __nv_bfloat16 smem[];

    const int tid = threadIdx.x;
    const int lane = tid & 31, warp = tid >> 5;
    const int z = blockIdx.z;
    const int blockM = blockIdx.y * 128, blockN = blockIdx.x * 128;
    const int m0 = (warp >> 1) * 32, n0 = (warp & 1) * 64;

    const __nv_bfloat16* Bh = (z == 0) ? Wqh : (z == 1) ? Wkh : Wvh;
    const __nv_bfloat16* Bl = (z == 0) ? Wql : (z == 1) ? Wkl : Wvl;

    const __nv_bfloat16* gAh = xh + (size_t)blockM * Kc;
    const __nv_bfloat16* gAl = xl + (size_t)blockM * Kc;
    const __nv_bfloat16* gBh = Bh + (size_t)blockN * Kc;
    const __nv_bfloat16* gBl = Bl + (size_t)blockN * Kc;

    float acc[2][8][4];
    float accS[2][4];
#pragma unroll
    for (int a = 0; a < 2; a++)
#pragma unroll
        for (int b = 0; b < 8; b++)
#pragma unroll
            for (int c = 0; c < 4; c++) acc[a][b][c] = 0.f;

    const int nk = Kc >> 5;
    load_tiles(smem, gAh, gAl, gBh, gBl, Kc, 0, tid);

    for (int i = 0; i < nk; i++) {
        if (i + 1 < nk) {
            load_tiles(smem + ((i + 1) & 1) * 16384, gAh, gAl, gBh, gBl,
                       Kc, (i + 1) << 5, tid);
            asm volatile("cp.async.wait_group 1;" ::: "memory");
        } else {
            asm volatile("cp.async.wait_group 0;" ::: "memory");
        }
        __syncthreads();
        compute_tiles<false>(smem + (i & 1) * 16384, acc, accS, m0, n0, lane);
        __syncthreads();
    }

#pragma unroll
    for (int mt = 0; mt < 2; mt++)
#pragma unroll
        for (int nt = 0; nt < 8; nt++) {
            const int gr = blockM + m0 + mt * 16 + (lane >> 2);
            const int gc = blockN + n0 + nt * 8 + ((lane & 3) << 1);
            const size_t i0 = qkv_idx(gr, gc);
            const size_t i1 = qkv_idx(gr + 8, gc);
            float c0 = acc[mt][nt][0], c1 = acc[mt][nt][1];
            float c2 = acc[mt][nt][2], c3 = acc[mt][nt][3];
            if (z == 2) {
                v32[i0] = c0; v32[i0 + 1] = c1;
                v32[i1] = c2; v32[i1 + 1] = c3;
            } else {
                c0 *= INV4; c1 *= INV4; c2 *= INV4; c3 *= INV4;
                __nv_bfloat16* Ch = (z == 0) ? qh : kh;
                __nv_bfloat16* Cl = (z == 0) ? ql : kl;
                split_store(Ch, Cl, i0, i1, c0, c1, c2, c3);
            }
        }
}

// ---------------------------------------------------------------------------
// fp32 -> (hi, lo) bf16 split, elementwise
// ---------------------------------------------------------------------------
__global__ void split_kernel(const float* __restrict__ src,
                             __nv_bfloat16* __restrict__ hi,
                             __nv_bfloat16* __restrict__ lo,
                             int n4)
{
    int i = blockIdx.x * blockDim.x + threadIdx.x;
    if (i >= n4) return;
    float4 v = ((const float4*)src)[i];
    float f[4] = {v.x, v.y, v.z, v.w};
    __nv_bfloat16 h[4], l[4];
#pragma unroll
    for (int j = 0; j < 4; j++) {
        h[j] = __float2bfloat16(f[j]);
        l[j] = __float2bfloat16(f[j] - __bfloat162float(h[j]));
    }
    ((__nv_bfloat162*)hi)[2 * i]     = __nv_bfloat162(h[0], h[1]);
    ((__nv_bfloat162*)hi)[2 * i + 1] = __nv_bfloat162(h[2], h[3]);
    ((__nv_bfloat162*)lo)[2 * i]     = __nv_bfloat162(l[0], l[1]);
    ((__nv_bfloat162*)lo)[2 * i + 1] = __nv_bfloat162(l[2], l[3]);
}

// ---------------------------------------------------------------------------
// fp32 [R][C] -> transposed (hi, lo) bf16 [C][R], batched over z
// ---------------------------------------------------------------------------
__global__ void tsplit_kernel(const float* __restrict__ src,
                              __nv_bfloat16* __restrict__ hi,
                              __nv_bfloat16* __restrict__ lo,
                              int R, int C)
{
    __shared__ float t[32][33];
    size_t zoff = (size_t)blockIdx.z * R * C;
    const float* s = src + zoff;
    __nv_bfloat16* ho = hi + zoff;
    __nv_bfloat16* lor = lo + zoff;
    int c0 = blockIdx.x * 32, r0 = blockIdx.y * 32;

#pragma unroll
    for (int i = 0; i < 4; i++) {
        int r = r0 + threadIdx.y + i * 8;
        t[threadIdx.y + i * 8][threadIdx.x] = s[(size_t)r * C + c0 + threadIdx.x];
    }
    __syncthreads();
#pragma unroll
    for (int i = 0; i < 4; i++) {
        int cc = c0 + threadIdx.y + i * 8;
        int rr = r0 + threadIdx.x;
        float v = t[threadIdx.x][threadIdx.y + i * 8];
        __nv_bfloat16 h = __float2bfloat16(v);
        ho[(size_t)cc * R + rr] = h;
        lor[(size_t)cc * R + rr] = __float2bfloat16(v - __bfloat162float(h));
    }
}

// Merged transpose+split of Wq, Wk, Wv (each [Kc][KH] -> [KH][Kc]).
__global__ void tsplitW3_kernel(const float* __restrict__ Wq,
                                const float* __restrict__ Wk,
                                const float* __restrict__ Wv,
                                __nv_bfloat16* __restrict__ qH, __nv_bfloat16* __restrict__ qL,
                                __nv_bfloat16* __restrict__ kH, __nv_bfloat16* __restrict__ kL,
                                __nv_bfloat16* __restrict__ vH, __nv_bfloat16* __restrict__ vL)
{
    __shared__ float t[32][33];
    const int z = blockIdx.z;
    const float* s = (z == 0) ? Wq : (z == 1) ? Wk : Wv;
    __nv_bfloat16* ho  = (z == 0) ? qH : (z == 1) ? kH : vH;
    __nv_bfloat16* lor = (z == 0) ? qL : (z == 1) ? kL : vL;
    int c0 = blockIdx.x * 32, r0 = blockIdx.y * 32;

#pragma unroll
    for (int i = 0; i < 4; i++) {
        int r = r0 + threadIdx.y + i * 8;
        t[threadIdx.y + i * 8][threadIdx.x] = s[(size_t)r * KH + c0 + threadIdx.x];
    }
    __syncthreads();
#pragma unroll
    for (int i = 0; i < 4; i++) {
        int cc = c0 + threadIdx.y + i * 8;
        int rr = r0 + threadIdx.x;
        float v = t[threadIdx.x][threadIdx.y + i * 8];
        __nv_bfloat16 h = __float2bfloat16(v);
        ho[(size_t)cc * Kc + rr] = h;
        lor[(size_t)cc * Kc + rr] = __float2bfloat16(v - __bfloat162float(h));
    }
}

// ---------------------------------------------------------------------------
// kernel_launch
// ---------------------------------------------------------------------------
#define GETSYM(var, sym) \
    { void* _p; cudaGetSymbolAddress(&_p, sym); var = decltype(var)(_p); }

extern "C" void kernel_launch(void* const* d_in, const int* in_sizes, int n_in,
                              void* d_out, int out_size)
{
    const float* x  = (const float*)d_in[0];
    const float* Wq = (const float*)d_in[1];
    const float* Wk = (const float*)d_in[2];
    const float* Wv = (const float*)d_in[3];
    const float* Wu = (const float*)d_in[4];
    const float* bu = (const float*)d_in[5];
    float* out = (float*)d_out;
    (void)in_sizes; (void)n_in; (void)out_size;

    cudaFuncSetAttribute(mma_gemm<false>, cudaFuncAttributeMaxDynamicSharedMemorySize, 65536);
    cudaFuncSetAttribute(mma_gemm<true>,  cudaFuncAttributeMaxDynamicSharedMemorySize, 65536);
    cudaFuncSetAttribute(qkv_gemm,        cudaFuncAttributeMaxDynamicSharedMemorySize, 65536);

    __nv_bfloat16 *xh, *xl, *WqTh, *WqTl, *WkTh, *WkTl, *WvTh, *WvTl, *WuTh, *WuTl;
    __nv_bfloat16 *qh, *ql, *kh, *kl, *vTh, *vTl, *eh, *el, *atth, *attl;
    float *v32;
    GETSYM(xh, g_xh); GETSYM(xl, g_xl);
    GETSYM(WqTh, g_WqTh); GETSYM(WqTl, g_WqTl);
    GETSYM(WkTh, g_WkTh); GETSYM(WkTl, g_WkTl);
    GETSYM(WvTh, g_WvTh); GETSYM(WvTl, g_WvTl);
    GETSYM(WuTh, g_WuTh); GETSYM(WuTl, g_WuTl);
    GETSYM(qh, g_qh); GETSYM(ql, g_ql); GETSYM(kh, g_kh); GETSYM(kl, g_kl);
    GETSYM(v32, g_v32); GETSYM(vTh, g_vTh); GETSYM(vTl, g_vTl);
    GETSYM(eh, g_eh); GETSYM(el, g_el);
    GETSYM(atth, g_atth); GETSYM(attl, g_attl);

    const dim3 tb(32, 8);

    // #0: x split
    split_kernel<<<(int)(NA / 4 / 256), 256>>>(x, xh, xl, (int)(NA / 4));
    // #1: Wq/Wk/Wv transpose+split (merged)
    tsplitW3_kernel<<<dim3(KH / 32, Kc / 32, 3), tb>>>(
        Wq, Wk, Wv, WqTh, WqTl, WkTh, WkTl, WvTh, WvTl);
    // #2: Wu transpose+split
    tsplit_kernel<<<dim3(Kc / 32, KH / 32, 1), tb>>>(Wu, WuTh, WuTl, KH, Kc);

    // #3: merged QKV projection (M=8192, N=4096, K=512, z=3)
    qkv_gemm<<<dim3(KH / 128, M0 / 128, 3), 256, 65536>>>(
        xh, xl, WqTh, WqTl, WkTh, WkTl, WvTh, WvTl, qh, ql, kh, kl, v32);

    // #4: v transpose+split per head
    tsplit_kernel<<<dim3(Kc / 32, Tc / 32, Bc * Hc), tb>>>(v32, vTh, vTl, Tc, Kc);

    // #5: scores -> exp(scores) split (M=N=2048, K=512, z=32)
    mma_gemm<false><<<dim3(Tc / 128, Tc / 128, Bc * Hc), 256, 65536>>>(
        qh, ql, kh, kl, nullptr, eh, el, nullptr,
        Kc, Tc, (size_t)Tc * Kc, (size_t)Tc * Kc, (size_t)Tc * Tc, 3, 1.f);

    // #6: PV with fused rowsum + normalization (M=2048, N=512, K=2048, z=32)
    mma_gemm<true><<<dim3(Kc / 128, Tc / 128, Bc * Hc), 256, 65536>>>(
        eh, el, vTh, vTl, nullptr, atth, attl, nullptr,
        Tc, 0, (size_t)Tc * Tc, (size_t)Kc * Tc, 0, 2, 1.f);

    // #7: output projection + bias (M=8192, N=512, K=4096)
    mma_gemm<false><<<dim3(Kc / 128, M0 / 128, 1), 256, 65536>>>(
        atth, attl, WuTh, WuTl, out, nullptr, nullptr, bu,
        KH, Kc, 0, 0, 0, 0, 1.f);
}